// round 9
// baseline (speedup 1.0000x reference)
#include <cuda_runtime.h>
#include <cuda_fp16.h>
#include <cstdint>

#define N_NODES 100000
#define N_EDGES 1250000
#define DFEAT   64
#define UNITS   64

#define E4      (N_EDGES / 4)                          // 312500
#define SCAN_B  1024
#define NB_SCAN ((N_NODES + SCAN_B - 1) / SCAN_B)      // 98

// ---- scratch (device globals; allocation-free) ----
__device__ __half2 g_U[(size_t)N_NODES * (UNITS / 2)]; // dinv[n]*(F[n]@W) fp16, 12.8 MB
__device__ int     g_degi[N_NODES];
__device__ float   g_dinv[N_NODES];
__device__ int     g_rowptr[N_NODES + 1];
__device__ int     g_fill[N_NODES];
__device__ int     g_col[N_EDGES];
__device__ int     g_is64;
// decoupled-lookback scan state
__device__ int     g_agg[NB_SCAN];
__device__ int     g_inc[NB_SCAN];
__device__ int     g_flag[NB_SCAN];   // 0=none, 1=aggregate, 2=inclusive

// f32x2 packed FMA helpers (Blackwell FFMA2)
#define FMA_F32X2(acc, a, b) \
    asm("fma.rn.f32x2 %0, %1, %2, %0;" : "+l"(acc) : "l"(a), "l"(b))
#define PACK_DUP_F32X2(out, s) \
    asm("mov.b64 %0, {%1, %1};" : "=l"(out) : "r"(s))

__device__ __forceinline__ void load_edges4(const void* __restrict__ ei,
                                            int t, size_t elem_off, int v[4], int is64) {
    if (is64) {
        const longlong2* p = (const longlong2*)((const long long*)ei + elem_off);
        longlong2 a = p[t * 2];
        longlong2 b = p[t * 2 + 1];
        v[0] = (int)a.x; v[1] = (int)a.y; v[2] = (int)b.x; v[3] = (int)b.y;
    } else {
        int4 a = ((const int4*)((const int*)ei + elem_off))[t];
        v[0] = a.x; v[1] = a.y; v[2] = a.z; v[3] = a.w;
    }
}

// ---------------------------------------------------------------------------
// K1: zero degree counters + scan flags + dtype detect
// ---------------------------------------------------------------------------
__global__ void k_zero_detect(const void* __restrict__ ei) {
    int i = blockIdx.x * blockDim.x + threadIdx.x;
    int stride = gridDim.x * blockDim.x;
    for (int j = i; j < N_NODES; j += stride) g_degi[j] = 0;
    if (i < NB_SCAN) { g_flag[i] = 0; g_agg[i] = 0; g_inc[i] = 0; }

    if (blockIdx.x == 0 && threadIdx.x < 32) {
        const long long* p = (const long long*)ei;
        int bad = 0;
#pragma unroll
        for (int k = 0; k < 8; k++) {
            long long v = p[threadIdx.x * 8 + k];
            bad |= (v < 0 || v >= N_NODES);
        }
        unsigned any = __ballot_sync(0xFFFFFFFFu, bad);
        if (threadIdx.x == 0) g_is64 = (any == 0u) ? 1 : 0;
    }
}

// ---------------------------------------------------------------------------
// K2: degree count (4 edges/thread)
// ---------------------------------------------------------------------------
__global__ void k_degree(const void* __restrict__ ei) {
    int t = blockIdx.x * blockDim.x + threadIdx.x;
    if (t >= E4) return;
    int r[4];
    load_edges4(ei, t, 0, r, g_is64);
#pragma unroll
    for (int k = 0; k < 4; k++) atomicAdd(&g_degi[r[k]], 1);
}

// ---------------------------------------------------------------------------
// K3: single-pass scan (decoupled lookback) + rowptr/fill/dinv finalize
// ---------------------------------------------------------------------------
__global__ void __launch_bounds__(SCAN_B)
k_scan() {
    __shared__ int s[SCAN_B];
    __shared__ int s_prefix;
    int tid = threadIdx.x;
    int bid = blockIdx.x;
    int i = bid * SCAN_B + tid;

    int d = (i < N_NODES) ? g_degi[i] : 0;
    s[tid] = d;
    __syncthreads();
#pragma unroll
    for (int off = 1; off < SCAN_B; off <<= 1) {
        int t = (tid >= off) ? s[tid - off] : 0;
        __syncthreads();
        s[tid] += t;
        __syncthreads();
    }
    int incl = s[tid];
    int block_total = s[SCAN_B - 1];

    if (tid == 0) {
        int prefix = 0;
        if (bid == 0) {
            atomicExch(&g_inc[0], block_total);
            __threadfence();
            atomicExch(&g_flag[0], 2);
        } else {
            atomicExch(&g_agg[bid], block_total);
            __threadfence();
            atomicExch(&g_flag[bid], 1);
            int p = bid - 1;
            while (p >= 0) {
                int f;
                while ((f = atomicAdd(&g_flag[p], 0)) == 0) __nanosleep(32);
                if (f == 2) { prefix += atomicAdd(&g_inc[p], 0); break; }
                prefix += atomicAdd(&g_agg[p], 0);
                p--;
            }
            atomicExch(&g_inc[bid], prefix + block_total);
            __threadfence();
            atomicExch(&g_flag[bid], 2);
        }
        s_prefix = prefix;
    }
    __syncthreads();

    if (i < N_NODES) {
        int excl = s_prefix + incl - d;
        g_rowptr[i] = excl;
        g_fill[i]   = excl;
        g_dinv[i]   = (d > 0) ? rsqrtf((float)d) : 0.f;
    }
    if (i == 0) g_rowptr[N_NODES] = N_EDGES;
}

// ---------------------------------------------------------------------------
// K4: transform — 2 threads per node; thread h computes outputs [h*32, h*32+32)
//     U[n] = fp16( dinv[n] * (F[n] @ W) ).  16 f32x2 accumulators (~80 regs).
// ---------------------------------------------------------------------------
__global__ void __launch_bounds__(256)
k_transform(const float* __restrict__ F, const float* __restrict__ W) {
    __shared__ float4 Ws[DFEAT * (UNITS / 4)];  // 16 KB
    for (int i = threadIdx.x; i < DFEAT * (UNITS / 4); i += 256)
        Ws[i] = reinterpret_cast<const float4*>(W)[i];
    __syncthreads();

    int gid = blockIdx.x * 256 + threadIdx.x;
    int node = gid >> 1;
    int h = gid & 1;                 // which half of the output row
    if (node >= N_NODES) return;

    unsigned long long acc[16];      // 16 f32x2 = 32 outputs
#pragma unroll
    for (int j = 0; j < 16; j++) acc[j] = 0ull;

    const float4* Frow = reinterpret_cast<const float4*>(F + (size_t)node * DFEAT);
#pragma unroll 4
    for (int k4 = 0; k4 < 16; k4++) {
        float4 f = Frow[k4];
        float fv[4] = {f.x, f.y, f.z, f.w};
#pragma unroll
        for (int kk = 0; kk < 4; kk++) {
            unsigned long long p2;
            PACK_DUP_F32X2(p2, __float_as_uint(fv[kk]));
            const unsigned long long* wrow =
                reinterpret_cast<const unsigned long long*>(&Ws[(k4 * 4 + kk) * 16 + h * 8]);
#pragma unroll
            for (int j = 0; j < 16; j++) FMA_F32X2(acc[j], p2, wrow[j]);
        }
    }
    float dv = g_dinv[node];
    __half2* Urow = &g_U[(size_t)node * 32 + h * 16];
#pragma unroll
    for (int j = 0; j < 16; j++) {
        float2 p = *reinterpret_cast<float2*>(&acc[j]);
        Urow[j] = __floats2half2_rn(p.x * dv, p.y * dv);
    }
}

// ---------------------------------------------------------------------------
// K5: CSR fill (4 edges/thread) — own launch, full occupancy
// ---------------------------------------------------------------------------
__global__ void k_fill(const void* __restrict__ ei) {
    int t = blockIdx.x * blockDim.x + threadIdx.x;
    if (t >= E4) return;
    const int is64 = g_is64;
    int r[4], c[4];
    load_edges4(ei, t, 0, r, is64);
    load_edges4(ei, t, N_EDGES, c, is64);
#pragma unroll
    for (int k = 0; k < 4; k++) {
        int pos = atomicAdd(&g_fill[r[k]], 1);
        g_col[pos] = c[k];
    }
}

// ---------------------------------------------------------------------------
// K6: gather + epilogue. 8 threads/node; thread h owns one uint4 (16B) of the
//     128B fp16 row. fp32 accumulation, no atomics.
// ---------------------------------------------------------------------------
__global__ void k_gather(float4* __restrict__ out4,
                         const float* __restrict__ bias) {
    int gid = blockIdx.x * blockDim.x + threadIdx.x;
    int node = gid >> 3;
    int h = gid & 7;
    if (node >= N_NODES) return;

    const uint4* Ub = reinterpret_cast<const uint4*>(g_U);  // 8 uint4 per row
    int start = g_rowptr[node];
    int end   = g_rowptr[node + 1];

    float2 a0 = make_float2(0.f, 0.f), a1 = a0, a2 = a0, a3 = a0;
    float2 b0 = a0, b1 = a0, b2 = a0, b3 = a0;

    int j = start;
    for (; j + 1 < end; j += 2) {
        int i0 = g_col[j];
        int i1 = g_col[j + 1];
        uint4 u = Ub[i0 * 8 + h];
        uint4 v = Ub[i1 * 8 + h];
        float2 f;
        f = __half22float2(*(__half2*)&u.x); a0.x += f.x; a0.y += f.y;
        f = __half22float2(*(__half2*)&u.y); a1.x += f.x; a1.y += f.y;
        f = __half22float2(*(__half2*)&u.z); a2.x += f.x; a2.y += f.y;
        f = __half22float2(*(__half2*)&u.w); a3.x += f.x; a3.y += f.y;
        f = __half22float2(*(__half2*)&v.x); b0.x += f.x; b0.y += f.y;
        f = __half22float2(*(__half2*)&v.y); b1.x += f.x; b1.y += f.y;
        f = __half22float2(*(__half2*)&v.z); b2.x += f.x; b2.y += f.y;
        f = __half22float2(*(__half2*)&v.w); b3.x += f.x; b3.y += f.y;
    }
    if (j < end) {
        uint4 u = Ub[g_col[j] * 8 + h];
        float2 f;
        f = __half22float2(*(__half2*)&u.x); a0.x += f.x; a0.y += f.y;
        f = __half22float2(*(__half2*)&u.y); a1.x += f.x; a1.y += f.y;
        f = __half22float2(*(__half2*)&u.z); a2.x += f.x; a2.y += f.y;
        f = __half22float2(*(__half2*)&u.w); a3.x += f.x; a3.y += f.y;
    }
    a0.x += b0.x; a0.y += b0.y;  a1.x += b1.x; a1.y += b1.y;
    a2.x += b2.x; a2.y += b2.y;  a3.x += b3.x; a3.y += b3.y;

    float dv = g_dinv[node];
    float4 bb0 = reinterpret_cast<const float4*>(bias)[h * 2];
    float4 bb1 = reinterpret_cast<const float4*>(bias)[h * 2 + 1];
    float4 v0, v1;
    v0.x = fmaxf(fmaf(dv, a0.x, bb0.x), 0.f);
    v0.y = fmaxf(fmaf(dv, a0.y, bb0.y), 0.f);
    v0.z = fmaxf(fmaf(dv, a1.x, bb0.z), 0.f);
    v0.w = fmaxf(fmaf(dv, a1.y, bb0.w), 0.f);
    v1.x = fmaxf(fmaf(dv, a2.x, bb1.x), 0.f);
    v1.y = fmaxf(fmaf(dv, a2.y, bb1.y), 0.f);
    v1.z = fmaxf(fmaf(dv, a3.x, bb1.z), 0.f);
    v1.w = fmaxf(fmaf(dv, a3.y, bb1.w), 0.f);
    out4[node * 16 + h * 2]     = v0;
    out4[node * 16 + h * 2 + 1] = v1;
}

// ---------------------------------------------------------------------------
extern "C" void kernel_launch(void* const* d_in, const int* in_sizes, int n_in,
                              void* d_out, int out_size) {
    const float* features = (const float*)d_in[0];       // [N, 64]
    const void*  edge_idx = d_in[1];                     // [2, E] int32 or int64
    const float* weight   = (const float*)d_in[2];       // [64, 64]
    const float* bias     = (const float*)d_in[3];       // [64]
    float4*      out4     = (float4*)d_out;              // [N, 64] fp32

    const int B = 256;

    k_zero_detect<<<512, B>>>(edge_idx);
    k_degree<<<(E4 + B - 1) / B, B>>>(edge_idx);
    k_scan<<<NB_SCAN, SCAN_B>>>();
    k_fill<<<(E4 + B - 1) / B, B>>>(edge_idx);
    k_transform<<<(N_NODES * 2 + B - 1) / B, B>>>(features, weight);
    k_gather<<<(N_NODES * 8 + B - 1) / B, B>>>(out4, bias);
}

// round 10
// speedup vs baseline: 1.2915x; 1.2915x over previous
#include <cuda_runtime.h>
#include <cuda_fp16.h>
#include <cstdint>

#define N_NODES 100000
#define N_EDGES 1250000
#define DFEAT   64
#define UNITS   64

#define E4      (N_EDGES / 4)                          // 312500
#define SCAN_B  1024
#define NB_SCAN ((N_NODES + SCAN_B - 1) / SCAN_B)      // 98

// ---- scratch (device globals; allocation-free) ----
__device__ __half2 g_U[(size_t)N_NODES * (UNITS / 2)]; // dinv[n]*(F[n]@W) fp16, 12.8 MB
__device__ int     g_degi[N_NODES];
__device__ float   g_dinv[N_NODES];
__device__ int     g_rowptr[N_NODES + 1];
__device__ int     g_rank[N_EDGES];                    // rank of edge within its row
__device__ int     g_col[N_EDGES];
__device__ int     g_is64;
// decoupled-lookback scan state
__device__ int     g_agg[NB_SCAN];
__device__ int     g_inc[NB_SCAN];
__device__ int     g_flag[NB_SCAN];   // 0=none, 1=aggregate, 2=inclusive

// f32x2 packed FMA helpers (Blackwell FFMA2)
#define FMA_F32X2(acc, a, b) \
    asm("fma.rn.f32x2 %0, %1, %2, %0;" : "+l"(acc) : "l"(a), "l"(b))
#define PACK_DUP_F32X2(out, s) \
    asm("mov.b64 %0, {%1, %1};" : "=l"(out) : "r"(s))

__device__ __forceinline__ void load_edges4(const void* __restrict__ ei,
                                            int t, size_t elem_off, int v[4], int is64) {
    if (is64) {
        const longlong2* p = (const longlong2*)((const long long*)ei + elem_off);
        longlong2 a = p[t * 2];
        longlong2 b = p[t * 2 + 1];
        v[0] = (int)a.x; v[1] = (int)a.y; v[2] = (int)b.x; v[3] = (int)b.y;
    } else {
        int4 a = ((const int4*)((const int*)ei + elem_off))[t];
        v[0] = a.x; v[1] = a.y; v[2] = a.z; v[3] = a.w;
    }
}

// ---------------------------------------------------------------------------
// K1: zero degree counters + scan flags + dtype detect
// ---------------------------------------------------------------------------
__global__ void k_zero_detect(const void* __restrict__ ei) {
    int i = blockIdx.x * blockDim.x + threadIdx.x;
    int stride = gridDim.x * blockDim.x;
    for (int j = i; j < N_NODES; j += stride) g_degi[j] = 0;
    if (i < NB_SCAN) { g_flag[i] = 0; g_agg[i] = 0; g_inc[i] = 0; }

    if (blockIdx.x == 0 && threadIdx.x < 32) {
        const long long* p = (const long long*)ei;
        int bad = 0;
#pragma unroll
        for (int k = 0; k < 8; k++) {
            long long v = p[threadIdx.x * 8 + k];
            bad |= (v < 0 || v >= N_NODES);
        }
        unsigned any = __ballot_sync(0xFFFFFFFFu, bad);
        if (threadIdx.x == 0) g_is64 = (any == 0u) ? 1 : 0;
    }
}

// ---------------------------------------------------------------------------
// K2: degree count + rank capture (the atomic return value IS the CSR rank)
// ---------------------------------------------------------------------------
__global__ void k_degree_rank(const void* __restrict__ ei) {
    int t = blockIdx.x * blockDim.x + threadIdx.x;
    if (t >= E4) return;
    int r[4];
    load_edges4(ei, t, 0, r, g_is64);
    int4 rk;
    rk.x = atomicAdd(&g_degi[r[0]], 1);
    rk.y = atomicAdd(&g_degi[r[1]], 1);
    rk.z = atomicAdd(&g_degi[r[2]], 1);
    rk.w = atomicAdd(&g_degi[r[3]], 1);
    reinterpret_cast<int4*>(g_rank)[t] = rk;
}

// ---------------------------------------------------------------------------
// K3: single-pass scan (decoupled lookback) -> rowptr + dinv
// ---------------------------------------------------------------------------
__global__ void __launch_bounds__(SCAN_B)
k_scan() {
    __shared__ int s[SCAN_B];
    __shared__ int s_prefix;
    int tid = threadIdx.x;
    int bid = blockIdx.x;
    int i = bid * SCAN_B + tid;

    int d = (i < N_NODES) ? g_degi[i] : 0;
    s[tid] = d;
    __syncthreads();
#pragma unroll
    for (int off = 1; off < SCAN_B; off <<= 1) {
        int t = (tid >= off) ? s[tid - off] : 0;
        __syncthreads();
        s[tid] += t;
        __syncthreads();
    }
    int incl = s[tid];
    int block_total = s[SCAN_B - 1];

    if (tid == 0) {
        int prefix = 0;
        if (bid == 0) {
            atomicExch(&g_inc[0], block_total);
            __threadfence();
            atomicExch(&g_flag[0], 2);
        } else {
            atomicExch(&g_agg[bid], block_total);
            __threadfence();
            atomicExch(&g_flag[bid], 1);
            int p = bid - 1;
            while (p >= 0) {
                int f;
                while ((f = atomicAdd(&g_flag[p], 0)) == 0) __nanosleep(32);
                if (f == 2) { prefix += atomicAdd(&g_inc[p], 0); break; }
                prefix += atomicAdd(&g_agg[p], 0);
                p--;
            }
            atomicExch(&g_inc[bid], prefix + block_total);
            __threadfence();
            atomicExch(&g_flag[bid], 2);
        }
        s_prefix = prefix;
    }
    __syncthreads();

    if (i < N_NODES) {
        g_rowptr[i] = s_prefix + incl - d;
        g_dinv[i]   = (d > 0) ? rsqrtf((float)d) : 0.f;
    }
    if (i == 0) g_rowptr[N_NODES] = N_EDGES;
}

// ---------------------------------------------------------------------------
// K4: CSR fill by precomputed rank — NO atomics, pure bandwidth
// ---------------------------------------------------------------------------
__global__ void k_fill(const void* __restrict__ ei) {
    int t = blockIdx.x * blockDim.x + threadIdx.x;
    if (t >= E4) return;
    const int is64 = g_is64;
    int r[4], c[4];
    load_edges4(ei, t, 0, r, is64);
    load_edges4(ei, t, N_EDGES, c, is64);
    int4 rk = reinterpret_cast<const int4*>(g_rank)[t];
    g_col[g_rowptr[r[0]] + rk.x] = c[0];
    g_col[g_rowptr[r[1]] + rk.y] = c[1];
    g_col[g_rowptr[r[2]] + rk.z] = c[2];
    g_col[g_rowptr[r[3]] + rk.w] = c[3];
}

// ---------------------------------------------------------------------------
// K5: transform — 1 thread per node (R4-proven loop), fp16 output
//     U[n] = fp16( dinv[n] * (F[n] @ W) )
// ---------------------------------------------------------------------------
__global__ void k_transform(const float* __restrict__ F,
                            const float* __restrict__ W) {
    __shared__ float4 Ws[DFEAT * (UNITS / 4)];  // 16 KB
    for (int i = threadIdx.x; i < DFEAT * (UNITS / 4); i += blockDim.x)
        Ws[i] = reinterpret_cast<const float4*>(W)[i];
    __syncthreads();

    int node = blockIdx.x * blockDim.x + threadIdx.x;
    if (node >= N_NODES) return;

    unsigned long long acc[32];   // 32 f32x2 pairs = 64 outputs
#pragma unroll
    for (int j = 0; j < 32; j++) acc[j] = 0ull;

    const float4* Frow = reinterpret_cast<const float4*>(F + (size_t)node * DFEAT);
#pragma unroll 4
    for (int k4 = 0; k4 < 16; k4++) {
        float4 f = Frow[k4];
        float fv[4] = {f.x, f.y, f.z, f.w};
#pragma unroll
        for (int kk = 0; kk < 4; kk++) {
            unsigned long long p2;
            PACK_DUP_F32X2(p2, __float_as_uint(fv[kk]));
            const unsigned long long* wrow =
                reinterpret_cast<const unsigned long long*>(&Ws[(k4 * 4 + kk) * 16]);
#pragma unroll
            for (int j = 0; j < 32; j++) FMA_F32X2(acc[j], p2, wrow[j]);
        }
    }
    float dv = g_dinv[node];
    uint4* Urow = reinterpret_cast<uint4*>(&g_U[(size_t)node * 32]);
#pragma unroll
    for (int q = 0; q < 8; q++) {
        uint4 o;
        float2 p0 = *reinterpret_cast<float2*>(&acc[4 * q]);
        float2 p1 = *reinterpret_cast<float2*>(&acc[4 * q + 1]);
        float2 p2f = *reinterpret_cast<float2*>(&acc[4 * q + 2]);
        float2 p3 = *reinterpret_cast<float2*>(&acc[4 * q + 3]);
        __half2 h0 = __floats2half2_rn(p0.x * dv, p0.y * dv);
        __half2 h1 = __floats2half2_rn(p1.x * dv, p1.y * dv);
        __half2 h2 = __floats2half2_rn(p2f.x * dv, p2f.y * dv);
        __half2 h3 = __floats2half2_rn(p3.x * dv, p3.y * dv);
        o.x = *reinterpret_cast<unsigned*>(&h0);
        o.y = *reinterpret_cast<unsigned*>(&h1);
        o.z = *reinterpret_cast<unsigned*>(&h2);
        o.w = *reinterpret_cast<unsigned*>(&h3);
        Urow[q] = o;
    }
}

// ---------------------------------------------------------------------------
// K6: gather + epilogue. 8 threads/node; thread h owns one uint4 (16B) of the
//     128B fp16 row. fp32 accumulation, no atomics.
// ---------------------------------------------------------------------------
__global__ void k_gather(float4* __restrict__ out4,
                         const float* __restrict__ bias) {
    int gid = blockIdx.x * blockDim.x + threadIdx.x;
    int node = gid >> 3;
    int h = gid & 7;
    if (node >= N_NODES) return;

    const uint4* Ub = reinterpret_cast<const uint4*>(g_U);  // 8 uint4 per row
    int start = g_rowptr[node];
    int end   = g_rowptr[node + 1];

    float2 a0 = make_float2(0.f, 0.f), a1 = a0, a2 = a0, a3 = a0;
    float2 b0 = a0, b1 = a0, b2 = a0, b3 = a0;

    int j = start;
    for (; j + 1 < end; j += 2) {
        int i0 = g_col[j];
        int i1 = g_col[j + 1];
        uint4 u = Ub[i0 * 8 + h];
        uint4 v = Ub[i1 * 8 + h];
        float2 f;
        f = __half22float2(*(__half2*)&u.x); a0.x += f.x; a0.y += f.y;
        f = __half22float2(*(__half2*)&u.y); a1.x += f.x; a1.y += f.y;
        f = __half22float2(*(__half2*)&u.z); a2.x += f.x; a2.y += f.y;
        f = __half22float2(*(__half2*)&u.w); a3.x += f.x; a3.y += f.y;
        f = __half22float2(*(__half2*)&v.x); b0.x += f.x; b0.y += f.y;
        f = __half22float2(*(__half2*)&v.y); b1.x += f.x; b1.y += f.y;
        f = __half22float2(*(__half2*)&v.z); b2.x += f.x; b2.y += f.y;
        f = __half22float2(*(__half2*)&v.w); b3.x += f.x; b3.y += f.y;
    }
    if (j < end) {
        uint4 u = Ub[g_col[j] * 8 + h];
        float2 f;
        f = __half22float2(*(__half2*)&u.x); a0.x += f.x; a0.y += f.y;
        f = __half22float2(*(__half2*)&u.y); a1.x += f.x; a1.y += f.y;
        f = __half22float2(*(__half2*)&u.z); a2.x += f.x; a2.y += f.y;
        f = __half22float2(*(__half2*)&u.w); a3.x += f.x; a3.y += f.y;
    }
    a0.x += b0.x; a0.y += b0.y;  a1.x += b1.x; a1.y += b1.y;
    a2.x += b2.x; a2.y += b2.y;  a3.x += b3.x; a3.y += b3.y;

    float dv = g_dinv[node];
    float4 bb0 = reinterpret_cast<const float4*>(bias)[h * 2];
    float4 bb1 = reinterpret_cast<const float4*>(bias)[h * 2 + 1];
    float4 v0, v1;
    v0.x = fmaxf(fmaf(dv, a0.x, bb0.x), 0.f);
    v0.y = fmaxf(fmaf(dv, a0.y, bb0.y), 0.f);
    v0.z = fmaxf(fmaf(dv, a1.x, bb0.z), 0.f);
    v0.w = fmaxf(fmaf(dv, a1.y, bb0.w), 0.f);
    v1.x = fmaxf(fmaf(dv, a2.x, bb1.x), 0.f);
    v1.y = fmaxf(fmaf(dv, a2.y, bb1.y), 0.f);
    v1.z = fmaxf(fmaf(dv, a3.x, bb1.z), 0.f);
    v1.w = fmaxf(fmaf(dv, a3.y, bb1.w), 0.f);
    out4[node * 16 + h * 2]     = v0;
    out4[node * 16 + h * 2 + 1] = v1;
}

// ---------------------------------------------------------------------------
extern "C" void kernel_launch(void* const* d_in, const int* in_sizes, int n_in,
                              void* d_out, int out_size) {
    const float* features = (const float*)d_in[0];       // [N, 64]
    const void*  edge_idx = d_in[1];                     // [2, E] int32 or int64
    const float* weight   = (const float*)d_in[2];       // [64, 64]
    const float* bias     = (const float*)d_in[3];       // [64]
    float4*      out4     = (float4*)d_out;              // [N, 64] fp32

    const int B = 256;

    k_zero_detect<<<512, B>>>(edge_idx);
    k_degree_rank<<<(E4 + B - 1) / B, B>>>(edge_idx);
    k_scan<<<NB_SCAN, SCAN_B>>>();
    k_fill<<<(E4 + B - 1) / B, B>>>(edge_idx);
    k_transform<<<(N_NODES + B - 1) / B, B>>>(features, weight);
    k_gather<<<(N_NODES * 8 + B - 1) / B, B>>>(out4, bias);
}

// round 11
// speedup vs baseline: 1.4185x; 1.0984x over previous
#include <cuda_runtime.h>
#include <cuda_fp16.h>
#include <cstdint>

#define N_NODES 100000
#define N_EDGES 1250000
#define DFEAT   64
#define UNITS   64

#define E4      (N_EDGES / 4)                          // 312500
#define SCAN_B  1024
#define NB_SCAN ((N_NODES + SCAN_B - 1) / SCAN_B)      // 98

#define FILLB   ((E4 + 255) / 256)                     // 1221 fill blocks
#define APPLYB  ((N_NODES * 8 + 255) / 256)            // 3125 apply blocks (uint4 granularity)

// ---- scratch (device globals; allocation-free) ----
__device__ __half2 g_U[(size_t)N_NODES * (UNITS / 2)]; // T=F@W fp16, then scaled in-place
__device__ int     g_degi[N_NODES];
__device__ float   g_dinv[N_NODES];
__device__ int     g_rowptr[N_NODES + 1];
__device__ int     g_rank[N_EDGES];
__device__ int     g_col[N_EDGES];
__device__ int     g_is64;
// decoupled-lookback scan state
__device__ int     g_agg[NB_SCAN];
__device__ int     g_inc[NB_SCAN];
__device__ int     g_flag[NB_SCAN];

// f32x2 packed FMA helpers (Blackwell FFMA2)
#define FMA_F32X2(acc, a, b) \
    asm("fma.rn.f32x2 %0, %1, %2, %0;" : "+l"(acc) : "l"(a), "l"(b))
#define PACK_DUP_F32X2(out, s) \
    asm("mov.b64 %0, {%1, %1};" : "=l"(out) : "r"(s))

__device__ __forceinline__ void load_edges4(const void* __restrict__ ei,
                                            int t, size_t elem_off, int v[4], int is64) {
    if (is64) {
        const longlong2* p = (const longlong2*)((const long long*)ei + elem_off);
        longlong2 a = p[t * 2];
        longlong2 b = p[t * 2 + 1];
        v[0] = (int)a.x; v[1] = (int)a.y; v[2] = (int)b.x; v[3] = (int)b.y;
    } else {
        int4 a = ((const int4*)((const int*)ei + elem_off))[t];
        v[0] = a.x; v[1] = a.y; v[2] = a.z; v[3] = a.w;
    }
}

// ---------------------------------------------------------------------------
// K1 (stream 0): zero degree counters + scan flags + dtype detect
// ---------------------------------------------------------------------------
__global__ void k_zero_detect(const void* __restrict__ ei) {
    int i = blockIdx.x * blockDim.x + threadIdx.x;
    int stride = gridDim.x * blockDim.x;
    for (int j = i; j < N_NODES; j += stride) g_degi[j] = 0;
    if (i < NB_SCAN) { g_flag[i] = 0; g_agg[i] = 0; g_inc[i] = 0; }

    if (blockIdx.x == 0 && threadIdx.x < 32) {
        const long long* p = (const long long*)ei;
        int bad = 0;
#pragma unroll
        for (int k = 0; k < 8; k++) {
            long long v = p[threadIdx.x * 8 + k];
            bad |= (v < 0 || v >= N_NODES);
        }
        unsigned any = __ballot_sync(0xFFFFFFFFu, bad);
        if (threadIdx.x == 0) g_is64 = (any == 0u) ? 1 : 0;
    }
}

// ---------------------------------------------------------------------------
// K2 (stream 0): degree count + rank capture
// ---------------------------------------------------------------------------
__global__ void k_degree_rank(const void* __restrict__ ei) {
    int t = blockIdx.x * blockDim.x + threadIdx.x;
    if (t >= E4) return;
    int r[4];
    load_edges4(ei, t, 0, r, g_is64);
    int4 rk;
    rk.x = atomicAdd(&g_degi[r[0]], 1);
    rk.y = atomicAdd(&g_degi[r[1]], 1);
    rk.z = atomicAdd(&g_degi[r[2]], 1);
    rk.w = atomicAdd(&g_degi[r[3]], 1);
    reinterpret_cast<int4*>(g_rank)[t] = rk;
}

// ---------------------------------------------------------------------------
// K3 (stream 0): single-pass scan (decoupled lookback) -> rowptr + dinv
// ---------------------------------------------------------------------------
__global__ void __launch_bounds__(SCAN_B)
k_scan() {
    __shared__ int s[SCAN_B];
    __shared__ int s_prefix;
    int tid = threadIdx.x;
    int bid = blockIdx.x;
    int i = bid * SCAN_B + tid;

    int d = (i < N_NODES) ? g_degi[i] : 0;
    s[tid] = d;
    __syncthreads();
#pragma unroll
    for (int off = 1; off < SCAN_B; off <<= 1) {
        int t = (tid >= off) ? s[tid - off] : 0;
        __syncthreads();
        s[tid] += t;
        __syncthreads();
    }
    int incl = s[tid];
    int block_total = s[SCAN_B - 1];

    if (tid == 0) {
        int prefix = 0;
        if (bid == 0) {
            atomicExch(&g_inc[0], block_total);
            __threadfence();
            atomicExch(&g_flag[0], 2);
        } else {
            atomicExch(&g_agg[bid], block_total);
            __threadfence();
            atomicExch(&g_flag[bid], 1);
            int p = bid - 1;
            while (p >= 0) {
                int f;
                while ((f = atomicAdd(&g_flag[p], 0)) == 0) __nanosleep(32);
                if (f == 2) { prefix += atomicAdd(&g_inc[p], 0); break; }
                prefix += atomicAdd(&g_agg[p], 0);
                p--;
            }
            atomicExch(&g_inc[bid], prefix + block_total);
            __threadfence();
            atomicExch(&g_flag[bid], 2);
        }
        s_prefix = prefix;
    }
    __syncthreads();

    if (i < N_NODES) {
        g_rowptr[i] = s_prefix + incl - d;
        g_dinv[i]   = (d > 0) ? rsqrtf((float)d) : 0.f;
    }
    if (i == 0) g_rowptr[N_NODES] = N_EDGES;
}

// ---------------------------------------------------------------------------
// K4 (stream 2, overlapped): T = fp16(F @ W)  — no dinv; scaled later
// ---------------------------------------------------------------------------
__global__ void k_transform(const float* __restrict__ F,
                            const float* __restrict__ W) {
    __shared__ float4 Ws[DFEAT * (UNITS / 4)];  // 16 KB
    for (int i = threadIdx.x; i < DFEAT * (UNITS / 4); i += blockDim.x)
        Ws[i] = reinterpret_cast<const float4*>(W)[i];
    __syncthreads();

    int node = blockIdx.x * blockDim.x + threadIdx.x;
    if (node >= N_NODES) return;

    unsigned long long acc[32];   // 32 f32x2 pairs = 64 outputs
#pragma unroll
    for (int j = 0; j < 32; j++) acc[j] = 0ull;

    const float4* Frow = reinterpret_cast<const float4*>(F + (size_t)node * DFEAT);
#pragma unroll 4
    for (int k4 = 0; k4 < 16; k4++) {
        float4 f = Frow[k4];
        float fv[4] = {f.x, f.y, f.z, f.w};
#pragma unroll
        for (int kk = 0; kk < 4; kk++) {
            unsigned long long p2;
            PACK_DUP_F32X2(p2, __float_as_uint(fv[kk]));
            const unsigned long long* wrow =
                reinterpret_cast<const unsigned long long*>(&Ws[(k4 * 4 + kk) * 16]);
#pragma unroll
            for (int j = 0; j < 32; j++) FMA_F32X2(acc[j], p2, wrow[j]);
        }
    }
    uint4* Urow = reinterpret_cast<uint4*>(&g_U[(size_t)node * 32]);
#pragma unroll
    for (int q = 0; q < 8; q++) {
        uint4 o;
        float2 p0 = *reinterpret_cast<float2*>(&acc[4 * q]);
        float2 p1 = *reinterpret_cast<float2*>(&acc[4 * q + 1]);
        float2 p2f = *reinterpret_cast<float2*>(&acc[4 * q + 2]);
        float2 p3 = *reinterpret_cast<float2*>(&acc[4 * q + 3]);
        __half2 h0 = __floats2half2_rn(p0.x, p0.y);
        __half2 h1 = __floats2half2_rn(p1.x, p1.y);
        __half2 h2 = __floats2half2_rn(p2f.x, p2f.y);
        __half2 h3 = __floats2half2_rn(p3.x, p3.y);
        o.x = *reinterpret_cast<unsigned*>(&h0);
        o.y = *reinterpret_cast<unsigned*>(&h1);
        o.z = *reinterpret_cast<unsigned*>(&h2);
        o.w = *reinterpret_cast<unsigned*>(&h3);
        Urow[q] = o;
    }
}

// ---------------------------------------------------------------------------
// K5 (stream 0, after join): block-split — CSR fill by rank (no atomics)
//   blocks [0, FILLB)  ∥  in-place U *= dinv[node]  blocks [FILLB, FILLB+APPLYB)
//   Both sides ~28 regs — no register-ceiling coupling.
// ---------------------------------------------------------------------------
__global__ void k_fillapply(const void* __restrict__ ei) {
    int tid = threadIdx.x;
    if (blockIdx.x < FILLB) {
        int t = blockIdx.x * 256 + tid;
        if (t >= E4) return;
        const int is64 = g_is64;
        int r[4], c[4];
        load_edges4(ei, t, 0, r, is64);
        load_edges4(ei, t, N_EDGES, c, is64);
        int4 rk = reinterpret_cast<const int4*>(g_rank)[t];
        g_col[g_rowptr[r[0]] + rk.x] = c[0];
        g_col[g_rowptr[r[1]] + rk.y] = c[1];
        g_col[g_rowptr[r[2]] + rk.z] = c[2];
        g_col[g_rowptr[r[3]] + rk.w] = c[3];
    } else {
        int idx = (blockIdx.x - FILLB) * 256 + tid;   // uint4 index, 8 per node
        if (idx >= N_NODES * 8) return;
        int node = idx >> 3;
        float dv = g_dinv[node];
        uint4* p = reinterpret_cast<uint4*>(g_U) + idx;
        uint4 u = *p;
        float2 f;
        __half2 h;
        f = __half22float2(*(__half2*)&u.x); h = __floats2half2_rn(f.x * dv, f.y * dv); u.x = *(unsigned*)&h;
        f = __half22float2(*(__half2*)&u.y); h = __floats2half2_rn(f.x * dv, f.y * dv); u.y = *(unsigned*)&h;
        f = __half22float2(*(__half2*)&u.z); h = __floats2half2_rn(f.x * dv, f.y * dv); u.z = *(unsigned*)&h;
        f = __half22float2(*(__half2*)&u.w); h = __floats2half2_rn(f.x * dv, f.y * dv); u.w = *(unsigned*)&h;
        *p = u;
    }
}

// ---------------------------------------------------------------------------
// K6 (stream 0): gather + epilogue. 8 threads/node, fp32 accumulation.
// ---------------------------------------------------------------------------
__global__ void k_gather(float4* __restrict__ out4,
                         const float* __restrict__ bias) {
    int gid = blockIdx.x * blockDim.x + threadIdx.x;
    int node = gid >> 3;
    int h = gid & 7;
    if (node >= N_NODES) return;

    const uint4* Ub = reinterpret_cast<const uint4*>(g_U);  // 8 uint4 per row
    int start = g_rowptr[node];
    int end   = g_rowptr[node + 1];

    float2 a0 = make_float2(0.f, 0.f), a1 = a0, a2 = a0, a3 = a0;
    float2 b0 = a0, b1 = a0, b2 = a0, b3 = a0;

    int j = start;
    for (; j + 1 < end; j += 2) {
        int i0 = g_col[j];
        int i1 = g_col[j + 1];
        uint4 u = Ub[i0 * 8 + h];
        uint4 v = Ub[i1 * 8 + h];
        float2 f;
        f = __half22float2(*(__half2*)&u.x); a0.x += f.x; a0.y += f.y;
        f = __half22float2(*(__half2*)&u.y); a1.x += f.x; a1.y += f.y;
        f = __half22float2(*(__half2*)&u.z); a2.x += f.x; a2.y += f.y;
        f = __half22float2(*(__half2*)&u.w); a3.x += f.x; a3.y += f.y;
        f = __half22float2(*(__half2*)&v.x); b0.x += f.x; b0.y += f.y;
        f = __half22float2(*(__half2*)&v.y); b1.x += f.x; b1.y += f.y;
        f = __half22float2(*(__half2*)&v.z); b2.x += f.x; b2.y += f.y;
        f = __half22float2(*(__half2*)&v.w); b3.x += f.x; b3.y += f.y;
    }
    if (j < end) {
        uint4 u = Ub[g_col[j] * 8 + h];
        float2 f;
        f = __half22float2(*(__half2*)&u.x); a0.x += f.x; a0.y += f.y;
        f = __half22float2(*(__half2*)&u.y); a1.x += f.x; a1.y += f.y;
        f = __half22float2(*(__half2*)&u.z); a2.x += f.x; a2.y += f.y;
        f = __half22float2(*(__half2*)&u.w); a3.x += f.x; a3.y += f.y;
    }
    a0.x += b0.x; a0.y += b0.y;  a1.x += b1.x; a1.y += b1.y;
    a2.x += b2.x; a2.y += b2.y;  a3.x += b3.x; a3.y += b3.y;

    float dv = g_dinv[node];
    float4 bb0 = reinterpret_cast<const float4*>(bias)[h * 2];
    float4 bb1 = reinterpret_cast<const float4*>(bias)[h * 2 + 1];
    float4 v0, v1;
    v0.x = fmaxf(fmaf(dv, a0.x, bb0.x), 0.f);
    v0.y = fmaxf(fmaf(dv, a0.y, bb0.y), 0.f);
    v0.z = fmaxf(fmaf(dv, a1.x, bb0.z), 0.f);
    v0.w = fmaxf(fmaf(dv, a1.y, bb0.w), 0.f);
    v1.x = fmaxf(fmaf(dv, a2.x, bb1.x), 0.f);
    v1.y = fmaxf(fmaf(dv, a2.y, bb1.y), 0.f);
    v1.z = fmaxf(fmaf(dv, a3.x, bb1.z), 0.f);
    v1.w = fmaxf(fmaf(dv, a3.y, bb1.w), 0.f);
    out4[node * 16 + h * 2]     = v0;
    out4[node * 16 + h * 2 + 1] = v1;
}

// ---------------------------------------------------------------------------
// Side stream + events, created once at static init (host objects; before the
// harness's memory-checkpoint baseline). No device memory allocation APIs.
// ---------------------------------------------------------------------------
static cudaStream_t g_s2;
static cudaEvent_t  g_evA, g_evB;
static struct SideStreamInit {
    SideStreamInit() {
        cudaStreamCreateWithFlags(&g_s2, cudaStreamNonBlocking);
        cudaEventCreateWithFlags(&g_evA, cudaEventDisableTiming);
        cudaEventCreateWithFlags(&g_evB, cudaEventDisableTiming);
    }
} g_side_init;

// ---------------------------------------------------------------------------
extern "C" void kernel_launch(void* const* d_in, const int* in_sizes, int n_in,
                              void* d_out, int out_size) {
    const float* features = (const float*)d_in[0];       // [N, 64]
    const void*  edge_idx = d_in[1];                     // [2, E] int32 or int64
    const float* weight   = (const float*)d_in[2];       // [64, 64]
    const float* bias     = (const float*)d_in[3];       // [64]
    float4*      out4     = (float4*)d_out;              // [N, 64] fp32

    const int B = 256;
    cudaStream_t s0 = 0;

    // fork: transform (independent of edges) runs on side stream
    cudaEventRecord(g_evA, s0);
    cudaStreamWaitEvent(g_s2, g_evA, 0);
    k_transform<<<(N_NODES + B - 1) / B, B, 0, g_s2>>>(features, weight);
    cudaEventRecord(g_evB, g_s2);

    // main chain on stream 0
    k_zero_detect<<<512, B>>>(edge_idx);
    k_degree_rank<<<(E4 + B - 1) / B, B>>>(edge_idx);
    k_scan<<<NB_SCAN, SCAN_B>>>();

    // join: fill needs rowptr (s0); applydinv needs dinv (s0) + T (s2)
    cudaStreamWaitEvent(s0, g_evB, 0);
    k_fillapply<<<FILLB + APPLYB, B>>>(edge_idx);
    k_gather<<<(N_NODES * 8 + B - 1) / B, B>>>(out4, bias);
}